// round 15
// baseline (speedup 1.0000x reference)
#include <cuda_runtime.h>
#include <cuda_bf16.h>
#include <cstdint>
#include <math.h>

#define T_TOK   4096
#define DMODEL  512
#define NEXP    8
#define DFF     2048
#define NASSIGN (T_TOK * 2)

// ---------------- device scratch ----------------
__device__ __nv_bfloat16 g_xnb[T_TOK * DMODEL];                 // 4 MB  normalized input (bf16)
__device__ __nv_bfloat16 g_hb[(size_t)NASSIGN * DFF];           // 32 MB gelu activations (bf16)
__device__ float         g_o[(size_t)NASSIGN * DMODEL];         // 16 MB weighted expert outputs
__device__ __nv_bfloat16 g_w1b[(size_t)NEXP * DMODEL * DFF];    // 16.8 MB
__device__ __nv_bfloat16 g_w2b[(size_t)NEXP * DFF * DMODEL];    // 16.8 MB
__device__ int   g_cnt[NEXP];          // zero-init at load; re-zeroed by k_combine each launch
__device__ int   g_list[NEXP * T_TOK];
__device__ float g_conf[NASSIGN];

// ---------------- helpers ----------------
__device__ __forceinline__ uint32_t sptr(const void* p) {
    return (uint32_t)__cvta_generic_to_shared(p);
}
__device__ __forceinline__ void cpasync16(uint32_t dst, const void* src, int srcsize) {
    asm volatile("cp.async.cg.shared.global [%0], [%1], 16, %2;\n"
                 :: "r"(dst), "l"(src), "r"(srcsize) : "memory");
}
__device__ __forceinline__ float gelu_f(float v) {
    float inner = 0.7978845608028654f * (v + 0.044715f * v * v * v);
    float t;
    asm("tanh.approx.f32 %0, %1;" : "=f"(t) : "f"(inner));
    return 0.5f * v * (1.0f + t);
}

#define LDSM4(R, addr) \
    asm volatile("ldmatrix.sync.aligned.m8n8.x4.shared.b16 {%0,%1,%2,%3}, [%4];" \
                 : "=r"(R[0]), "=r"(R[1]), "=r"(R[2]), "=r"(R[3]) : "r"(addr))
#define LDSM4T(R, addr) \
    asm volatile("ldmatrix.sync.aligned.m8n8.x4.trans.shared.b16 {%0,%1,%2,%3}, [%4];" \
                 : "=r"(R[0]), "=r"(R[1]), "=r"(R[2]), "=r"(R[3]) : "r"(addr))
#define MMA16816(C, A, B0, B1) \
    asm volatile("mma.sync.aligned.m16n8k16.row.col.f32.bf16.bf16.f32 " \
                 "{%0,%1,%2,%3}, {%4,%5,%6,%7}, {%8,%9}, {%0,%1,%2,%3};" \
                 : "+f"(C[0]), "+f"(C[1]), "+f"(C[2]), "+f"(C[3]) \
                 : "r"(A[0]), "r"(A[1]), "r"(A[2]), "r"(A[3]), "r"(B0), "r"(B1))

// smem staging (dynamic): 3-stage pipeline, BK=64
#define A_ST 18432              /* 128 rows x 72 bf16 (64 data + 8 pad) */
#define B_ST 17408              /* 64 rows x 136 bf16 */
#define OFF_B    (3 * A_ST)     /* 55296 */
#define OFF_BIAS (OFF_B + 3 * B_ST)   /* 107520 */
#define OFF_AID  (OFF_BIAS + 512)     /* 108032 */
#define SMEM_DYN (OFF_AID + 512)      /* 108544 */

// ---------------- K1: LayerNorm + router (one WARP per token, float4) + W1 cvt ----------------
// 256 threads = 8 warps = 8 tokens per block; 512 blocks.
__global__ void k_ln_router(const float* __restrict__ x, const float* __restrict__ Wg,
                            const float* __restrict__ ln_g, const float* __restrict__ ln_b,
                            const float* __restrict__ W1) {
    const int warp = threadIdx.x >> 5, lane = threadIdx.x & 31;
    const int t = blockIdx.x * 8 + warp;
    const float4* xr4 = (const float4*)(x + (size_t)t * DMODEL);   // 128 float4

    float4 v[4];
#pragma unroll
    for (int i = 0; i < 4; i++) v[i] = xr4[lane + 32 * i];

    float s = 0.0f;
#pragma unroll
    for (int i = 0; i < 4; i++) s += (v[i].x + v[i].y) + (v[i].z + v[i].w);
#pragma unroll
    for (int off = 16; off > 0; off >>= 1) s += __shfl_xor_sync(0xffffffffu, s, off);
    float mean = s * (1.0f / DMODEL);

    float s2 = 0.0f;
#pragma unroll
    for (int i = 0; i < 4; i++) {
        float dx = v[i].x - mean, dy = v[i].y - mean, dz = v[i].z - mean, dw = v[i].w - mean;
        s2 += dx * dx + dy * dy + dz * dz + dw * dw;
    }
#pragma unroll
    for (int off = 16; off > 0; off >>= 1) s2 += __shfl_xor_sync(0xffffffffu, s2, off);
    float rstd = rsqrtf(s2 * (1.0f / DMODEL) + 1e-5f);

    const float4* g4 = (const float4*)ln_g;
    const float4* b4 = (const float4*)ln_b;
    float4 xn[4];
    uint2* xnb4 = (uint2*)(g_xnb + (size_t)t * DMODEL);   // 4 bf16 = 8B per slot
#pragma unroll
    for (int i = 0; i < 4; i++) {
        int d4 = lane + 32 * i;
        float4 g = g4[d4], b = b4[d4];
        xn[i].x = (v[i].x - mean) * rstd * g.x + b.x;
        xn[i].y = (v[i].y - mean) * rstd * g.y + b.y;
        xn[i].z = (v[i].z - mean) * rstd * g.z + b.z;
        xn[i].w = (v[i].w - mean) * rstd * g.w + b.w;
        __nv_bfloat162 lo = __floats2bfloat162_rn(xn[i].x, xn[i].y);
        __nv_bfloat162 hi = __floats2bfloat162_rn(xn[i].z, xn[i].w);
        uint2 packed;
        packed.x = *(uint32_t*)&lo;
        packed.y = *(uint32_t*)&hi;
        xnb4[d4] = packed;
    }

    // router logits: for each of 16 elements (4 per float4), dot with Wg row (8 floats)
    float p[NEXP];
#pragma unroll
    for (int e = 0; e < NEXP; e++) p[e] = 0.0f;
#pragma unroll
    for (int i = 0; i < 4; i++) {
        int d0 = (lane + 32 * i) * 4;
        const float* xv = (const float*)&xn[i];
#pragma unroll
        for (int c = 0; c < 4; c++) {
            const float4* wr = (const float4*)(Wg + (size_t)(d0 + c) * NEXP);
            float4 w0 = wr[0], w1 = wr[1];
            float xe = xv[c];
            p[0] += xe * w0.x; p[1] += xe * w0.y;
            p[2] += xe * w0.z; p[3] += xe * w0.w;
            p[4] += xe * w1.x; p[5] += xe * w1.y;
            p[6] += xe * w1.z; p[7] += xe * w1.w;
        }
    }
#pragma unroll
    for (int e = 0; e < NEXP; e++) {
#pragma unroll
        for (int off = 16; off > 0; off >>= 1)
            p[e] += __shfl_xor_sync(0xffffffffu, p[e], off);
    }

    if (lane == 0) {
        int i0 = 0;
#pragma unroll
        for (int e = 1; e < NEXP; e++) if (p[e] > p[i0]) i0 = e;
        int i1 = -1;
#pragma unroll
        for (int e = 0; e < NEXP; e++) {
            if (e == i0) continue;
            if (i1 < 0 || p[e] > p[i1]) i1 = e;
        }
        float c0 = 1.0f / (1.0f + expf(p[i1] - p[i0]));
        float c1 = 1.0f - c0;
        int a0 = t * 2, a1 = t * 2 + 1;
        g_conf[a0] = c0;
        g_conf[a1] = c1;
        int p0 = atomicAdd(&g_cnt[i0], 1);
        g_list[i0 * T_TOK + p0] = a0;
        int p1 = atomicAdd(&g_cnt[i1], 1);
        g_list[i1 * T_TOK + p1] = a1;
    }

    // ---- W1 cvt: 8.39M elems / (512 blk * 256 thr * 4/chunk) = 16 chunks/thread ----
    {
        const size_t NW = (size_t)NEXP * DMODEL * DFF;
        size_t idx = ((size_t)blockIdx.x * 256 + threadIdx.x) * 4;
        const size_t stride = (size_t)512 * 256 * 4;
#pragma unroll 4
        for (; idx < NW; idx += stride) {
            float4 a = *(const float4*)(W1 + idx);
            __nv_bfloat162* p1 = (__nv_bfloat162*)(g_w1b + idx);
            p1[0] = __floats2bfloat162_rn(a.x, a.y);
            p1[1] = __floats2bfloat162_rn(a.z, a.w);
        }
    }
}

// ---------------- tensor-core routed GEMM: BK=64, 3-stage, single barrier/iter ----------------
// BM=128, BN=128, 256 threads (8 warps: 4m x 2n), warp tile 32x64.  (R10/R12 machinery)
// ffn1 additionally carries blockIdx.z == NEXP worker blocks that convert W2 fp32->bf16.
template<int KDIM, int LDB, bool IS_FFN1>
__global__ void __launch_bounds__(256, 2)
k_ffn(const float* __restrict__ bias, const float* __restrict__ w2src) {
    extern __shared__ char smem[];
    const int e = blockIdx.z;

    if (IS_FFN1 && e == NEXP) {
        // W2 cvt worker: 512 blocks x 256 threads, 16 float4 chunks each
        const size_t NW = (size_t)NEXP * DFF * DMODEL;
        size_t idx = ((size_t)(blockIdx.y * gridDim.x + blockIdx.x) * 256 + threadIdx.x) * 4;
        const size_t stride = (size_t)gridDim.x * gridDim.y * 256 * 4;
#pragma unroll 4
        for (; idx < NW; idx += stride) {
            float4 b = *(const float4*)(w2src + idx);
            __nv_bfloat162* p2 = (__nv_bfloat162*)(g_w2b + idx);
            p2[0] = __floats2bfloat162_rn(b.x, b.y);
            p2[1] = __floats2bfloat162_rn(b.z, b.w);
        }
        return;
    }

    const int cnt = g_cnt[e];
    const int row0 = blockIdx.y * 128;
    if (row0 >= cnt) return;
    const int n0 = blockIdx.x * 128;
    const int tid = threadIdx.x;
    const int lane = tid & 31, warp = tid >> 5;
    const int wm = warp & 3, wn = warp >> 2;

    float* s_bias = (float*)(smem + OFF_BIAS);
    int*   s_aid  = (int*)(smem + OFF_AID);

    const __nv_bfloat16* Asrc = IS_FFN1 ? g_xnb : g_hb;
    const __nv_bfloat16* W    = (IS_FFN1 ? g_w1b : g_w2b) + (size_t)e * KDIM * LDB;

    if (tid < 128) {
        int r = row0 + tid;
        s_aid[tid]  = (r < cnt) ? g_list[e * T_TOK + r] : -1;
        s_bias[tid] = bias[e * LDB + n0 + tid];
    }
    __syncthreads();

    const uint32_t sA = sptr(smem);
    const uint32_t sB = sA + OFF_B;

    // per-thread load slots: A 1024 chunks (128 rows x 8), B 1024 chunks (64 rows x 16)
    const __nv_bfloat16* aptr[4]; int asz[4]; uint32_t aoff[4];
    const __nv_bfloat16* bptr[4]; uint32_t boff[4];
#pragma unroll
    for (int j = 0; j < 4; j++) {
        int c = tid + j * 256;
        int r = c >> 3;                 // 8 x 16B chunks per 64-col A row
        int cc = (c & 7) * 8;
        int aid = s_aid[r];
        if (aid >= 0) {
            size_t rowbase = IS_FFN1 ? (size_t)(aid >> 1) * DMODEL : (size_t)aid * DFF;
            aptr[j] = Asrc + rowbase + cc;
            asz[j] = 16;
        } else {
            aptr[j] = Asrc;
            asz[j] = 0;
        }
        aoff[j] = (uint32_t)(r * 72 + cc) * 2;

        int rb = c >> 4;                // 16 x 16B chunks per 128-col B row (64 k-rows)
        int ccb = (c & 15) * 8;
        bptr[j] = W + (size_t)rb * LDB + n0 + ccb;
        boff[j] = (uint32_t)(rb * 136 + ccb) * 2;
    }

    auto load_tiles = [&](int it, int stage) {
        int k0 = it * 64;
#pragma unroll
        for (int j = 0; j < 4; j++)
            cpasync16(sA + stage * A_ST + aoff[j], aptr[j] + k0, asz[j]);
#pragma unroll
        for (int j = 0; j < 4; j++)
            cpasync16(sB + stage * B_ST + boff[j], bptr[j] + (size_t)k0 * LDB, 16);
        asm volatile("cp.async.commit_group;\n" ::: "memory");
    };

    float acc[2][8][4] = {};

    constexpr int KT = KDIM / 64;
    load_tiles(0, 0);
    load_tiles(1, 1);
    int stage_w = 2;   // next stage to fill
    int stage_c = 0;   // stage being computed

#pragma unroll 1
    for (int it = 0; it < KT; it++) {
        if (it) __syncthreads();   // all warps done reading the stage about to be overwritten
        if (it + 2 < KT) {
            load_tiles(it + 2, stage_w);
            if (++stage_w == 3) stage_w = 0;
            asm volatile("cp.async.wait_group 2;\n" ::: "memory");
        } else if (it + 1 < KT) {
            asm volatile("cp.async.wait_group 1;\n" ::: "memory");
        } else {
            asm volatile("cp.async.wait_group 0;\n" ::: "memory");
        }
        __syncthreads();   // data of stage_c visible to all warps

        const uint32_t aBase = sA + stage_c * A_ST;
        const uint32_t bBase = sB + stage_c * B_ST;
        if (++stage_c == 3) stage_c = 0;

#pragma unroll
        for (int kk = 0; kk < 64; kk += 16) {
            uint32_t a[2][4], b[4][4];
#pragma unroll
            for (int mi = 0; mi < 2; mi++) {
                int row = wm * 32 + mi * 16 + (lane & 15);
                uint32_t addr = aBase + (uint32_t)(row * 72 + kk) * 2 + (lane >> 4) * 16;
                LDSM4(a[mi], addr);
            }
#pragma unroll
            for (int nj = 0; nj < 4; nj++) {
                int krow = kk + (lane & 15);
                int col = wn * 64 + nj * 16 + (lane >> 4) * 8;
                uint32_t addr = bBase + (uint32_t)(krow * 136 + col) * 2;
                LDSM4T(b[nj], addr);
            }
#pragma unroll
            for (int mi = 0; mi < 2; mi++)
#pragma unroll
                for (int ni = 0; ni < 8; ni++)
                    MMA16816(acc[mi][ni], a[mi], b[ni >> 1][(ni & 1) * 2], b[ni >> 1][(ni & 1) * 2 + 1]);
        }
    }

    // epilogue
#pragma unroll
    for (int mi = 0; mi < 2; mi++) {
#pragma unroll
        for (int half = 0; half < 2; half++) {
            int rl = wm * 32 + mi * 16 + (lane >> 2) + half * 8;
            if (row0 + rl >= cnt) continue;
            int aid = s_aid[rl];
            if (IS_FFN1) {
                __nv_bfloat16* hrow = g_hb + (size_t)aid * DFF + n0;
#pragma unroll
                for (int ni = 0; ni < 8; ni++) {
                    int col = wn * 64 + ni * 8 + (lane & 3) * 2;
                    float v0 = gelu_f(acc[mi][ni][half * 2 + 0] + s_bias[col]);
                    float v1 = gelu_f(acc[mi][ni][half * 2 + 1] + s_bias[col + 1]);
                    *(__nv_bfloat162*)(hrow + col) = __floats2bfloat162_rn(v0, v1);
                }
            } else {
                float cf = g_conf[aid];
                float* orow = g_o + (size_t)aid * DMODEL + n0;
#pragma unroll
                for (int ni = 0; ni < 8; ni++) {
                    int col = wn * 64 + ni * 8 + (lane & 3) * 2;
                    float2 v;
                    v.x = cf * (acc[mi][ni][half * 2 + 0] + s_bias[col]);
                    v.y = cf * (acc[mi][ni][half * 2 + 1] + s_bias[col + 1]);
                    *(float2*)(orow + col) = v;
                }
            }
        }
    }
}

// ---------------- K4: combine + residual + post-LN, one WARP per token (float4) ----------------
// Block 0 also re-zeroes g_cnt for the next graph replay.
__global__ void k_combine(const float* __restrict__ x, const float* __restrict__ out_g,
                          const float* __restrict__ out_b, float* __restrict__ out) {
    if (blockIdx.x == 0 && threadIdx.x < NEXP) g_cnt[threadIdx.x] = 0;

    const int warp = threadIdx.x >> 5, lane = threadIdx.x & 31;
    const int t = blockIdx.x * 8 + warp;
    const float4* o04 = (const float4*)(g_o + (size_t)(t * 2) * DMODEL);
    const float4* o14 = o04 + DMODEL / 4;
    const float4* xr4 = (const float4*)(x + (size_t)t * DMODEL);

    float4 y[4];
#pragma unroll
    for (int i = 0; i < 4; i++) {
        int d4 = lane + 32 * i;
        float4 a = xr4[d4], b = o04[d4], c = o14[d4];
        y[i].x = a.x + b.x + c.x;
        y[i].y = a.y + b.y + c.y;
        y[i].z = a.z + b.z + c.z;
        y[i].w = a.w + b.w + c.w;
    }

    float s = 0.0f;
#pragma unroll
    for (int i = 0; i < 4; i++) s += (y[i].x + y[i].y) + (y[i].z + y[i].w);
#pragma unroll
    for (int off = 16; off > 0; off >>= 1) s += __shfl_xor_sync(0xffffffffu, s, off);
    float mean = s * (1.0f / DMODEL);

    float s2 = 0.0f;
#pragma unroll
    for (int i = 0; i < 4; i++) {
        float dx = y[i].x - mean, dy = y[i].y - mean, dz = y[i].z - mean, dw = y[i].w - mean;
        s2 += dx * dx + dy * dy + dz * dz + dw * dw;
    }
#pragma unroll
    for (int off = 16; off > 0; off >>= 1) s2 += __shfl_xor_sync(0xffffffffu, s2, off);
    float rstd = rsqrtf(s2 * (1.0f / DMODEL) + 1e-5f);

    const float4* g4 = (const float4*)out_g;
    const float4* b4 = (const float4*)out_b;
    float4* orow4 = (float4*)(out + (size_t)t * DMODEL);
#pragma unroll
    for (int i = 0; i < 4; i++) {
        int d4 = lane + 32 * i;
        float4 g = g4[d4], b = b4[d4];
        float4 o;
        o.x = (y[i].x - mean) * rstd * g.x + b.x;
        o.y = (y[i].y - mean) * rstd * g.y + b.y;
        o.z = (y[i].z - mean) * rstd * g.z + b.z;
        o.w = (y[i].w - mean) * rstd * g.w + b.w;
        orow4[d4] = o;
    }
}

// ---------------- launch ----------------
extern "C" void kernel_launch(void* const* d_in, const int* in_sizes, int n_in,
                              void* d_out, int out_size) {
    const float* x     = (const float*)d_in[0];
    const float* Wg    = (const float*)d_in[1];
    const float* W1    = (const float*)d_in[2];
    const float* b1    = (const float*)d_in[3];
    const float* W2    = (const float*)d_in[4];
    const float* b2    = (const float*)d_in[5];
    const float* ln_g  = (const float*)d_in[6];
    const float* ln_b  = (const float*)d_in[7];
    const float* out_g = (const float*)d_in[8];
    const float* out_b = (const float*)d_in[9];
    float* out = (float*)d_out;

    cudaFuncSetAttribute(k_ffn<DMODEL, DFF, true>,
                         cudaFuncAttributeMaxDynamicSharedMemorySize, SMEM_DYN);
    cudaFuncSetAttribute(k_ffn<DFF, DMODEL, false>,
                         cudaFuncAttributeMaxDynamicSharedMemorySize, SMEM_DYN);

    k_ln_router<<<T_TOK / 8, 256>>>(x, Wg, ln_g, ln_b, W1);

    dim3 g1(DFF / 128, T_TOK / 128, NEXP + 1);   // 16 x 32 x 9 (z=8 -> W2 cvt workers)
    k_ffn<DMODEL, DFF, true><<<g1, 256, SMEM_DYN>>>(b1, W2);

    dim3 g2(DMODEL / 128, T_TOK / 128, NEXP);    // 4 x 32 x 8
    k_ffn<DFF, DMODEL, false><<<g2, 256, SMEM_DYN>>>(b2, nullptr);

    k_combine<<<T_TOK / 8, 256>>>(x, out_g, out_b, out);
}

// round 16
// speedup vs baseline: 1.0376x; 1.0376x over previous
#include <cuda_runtime.h>
#include <cuda_bf16.h>
#include <cstdint>
#include <math.h>

#define T_TOK   4096
#define DMODEL  512
#define NEXP    8
#define DFF     2048
#define NASSIGN (T_TOK * 2)

// ---------------- device scratch ----------------
__device__ __nv_bfloat16 g_xnb[T_TOK * DMODEL];                 // 4 MB  normalized input (bf16)
__device__ __nv_bfloat16 g_hb[(size_t)NASSIGN * DFF];           // 32 MB gelu activations (bf16)
__device__ float         g_o[(size_t)NASSIGN * DMODEL];         // 16 MB weighted expert outputs
__device__ __nv_bfloat16 g_w1b[(size_t)NEXP * DMODEL * DFF];    // 16.8 MB
__device__ __nv_bfloat16 g_w2b[(size_t)NEXP * DFF * DMODEL];    // 16.8 MB
__device__ int   g_cnt[NEXP];          // zero-init at load; re-zeroed by k_combine each launch
__device__ int   g_list[NEXP * T_TOK];
__device__ float g_conf[NASSIGN];

// ---------------- helpers ----------------
__device__ __forceinline__ uint32_t sptr(const void* p) {
    return (uint32_t)__cvta_generic_to_shared(p);
}
__device__ __forceinline__ void cpasync16(uint32_t dst, const void* src, int srcsize) {
    asm volatile("cp.async.cg.shared.global [%0], [%1], 16, %2;\n"
                 :: "r"(dst), "l"(src), "r"(srcsize) : "memory");
}
__device__ __forceinline__ float gelu_f(float v) {
    float inner = 0.7978845608028654f * (v + 0.044715f * v * v * v);
    float t;
    asm("tanh.approx.f32 %0, %1;" : "=f"(t) : "f"(inner));
    return 0.5f * v * (1.0f + t);
}

#define LDSM4(R, addr) \
    asm volatile("ldmatrix.sync.aligned.m8n8.x4.shared.b16 {%0,%1,%2,%3}, [%4];" \
                 : "=r"(R[0]), "=r"(R[1]), "=r"(R[2]), "=r"(R[3]) : "r"(addr))
#define LDSM4T(R, addr) \
    asm volatile("ldmatrix.sync.aligned.m8n8.x4.trans.shared.b16 {%0,%1,%2,%3}, [%4];" \
                 : "=r"(R[0]), "=r"(R[1]), "=r"(R[2]), "=r"(R[3]) : "r"(addr))
#define MMA16816(C, A, B0, B1) \
    asm volatile("mma.sync.aligned.m16n8k16.row.col.f32.bf16.bf16.f32 " \
                 "{%0,%1,%2,%3}, {%4,%5,%6,%7}, {%8,%9}, {%0,%1,%2,%3};" \
                 : "+f"(C[0]), "+f"(C[1]), "+f"(C[2]), "+f"(C[3]) \
                 : "r"(A[0]), "r"(A[1]), "r"(A[2]), "r"(A[3]), "r"(B0), "r"(B1))

// smem staging (dynamic): 3-stage pipeline, BK=64
#define A_ST 18432              /* 128 rows x 72 bf16 (64 data + 8 pad) */
#define B_ST 17408              /* 64 rows x 136 bf16 */
#define OFF_B    (3 * A_ST)     /* 55296 */
#define OFF_BIAS (OFF_B + 3 * B_ST)   /* 107520 */
#define OFF_AID  (OFF_BIAS + 512)     /* 108032 */
#define SMEM_DYN (OFF_AID + 512)      /* 108544 */

// ---------------- K1: LayerNorm + router (one WARP per token) + W1 cvt ----------------
// 256 threads = 8 warps = 8 tokens per block; 512 blocks.  (R14 version — measured best)
__global__ void k_ln_router(const float* __restrict__ x, const float* __restrict__ Wg,
                            const float* __restrict__ ln_g, const float* __restrict__ ln_b,
                            const float* __restrict__ W1) {
    const int warp = threadIdx.x >> 5, lane = threadIdx.x & 31;
    const int t = blockIdx.x * 8 + warp;
    const float* xr = x + (size_t)t * DMODEL;

    float v[16];
#pragma unroll
    for (int i = 0; i < 16; i++) v[i] = xr[lane + 32 * i];

    float s = 0.0f;
#pragma unroll
    for (int i = 0; i < 16; i++) s += v[i];
#pragma unroll
    for (int off = 16; off > 0; off >>= 1) s += __shfl_xor_sync(0xffffffffu, s, off);
    float mean = s * (1.0f / DMODEL);

    float s2 = 0.0f;
#pragma unroll
    for (int i = 0; i < 16; i++) { float d = v[i] - mean; s2 += d * d; }
#pragma unroll
    for (int off = 16; off > 0; off >>= 1) s2 += __shfl_xor_sync(0xffffffffu, s2, off);
    float rstd = rsqrtf(s2 * (1.0f / DMODEL) + 1e-5f);

    float xn[16];
    __nv_bfloat16* xnb = g_xnb + (size_t)t * DMODEL;
#pragma unroll
    for (int i = 0; i < 16; i++) {
        int d = lane + 32 * i;
        xn[i] = (v[i] - mean) * rstd * ln_g[d] + ln_b[d];
        xnb[d] = __float2bfloat16(xn[i]);
    }

    float p[NEXP];
#pragma unroll
    for (int e = 0; e < NEXP; e++) p[e] = 0.0f;
#pragma unroll
    for (int i = 0; i < 16; i++) {
        const float4* wr = (const float4*)(Wg + (size_t)(lane + 32 * i) * NEXP);
        float4 w0 = wr[0], w1 = wr[1];
        p[0] += xn[i] * w0.x; p[1] += xn[i] * w0.y;
        p[2] += xn[i] * w0.z; p[3] += xn[i] * w0.w;
        p[4] += xn[i] * w1.x; p[5] += xn[i] * w1.y;
        p[6] += xn[i] * w1.z; p[7] += xn[i] * w1.w;
    }
#pragma unroll
    for (int e = 0; e < NEXP; e++) {
#pragma unroll
        for (int off = 16; off > 0; off >>= 1)
            p[e] += __shfl_xor_sync(0xffffffffu, p[e], off);
    }

    if (lane == 0) {
        int i0 = 0;
#pragma unroll
        for (int e = 1; e < NEXP; e++) if (p[e] > p[i0]) i0 = e;
        int i1 = -1;
#pragma unroll
        for (int e = 0; e < NEXP; e++) {
            if (e == i0) continue;
            if (i1 < 0 || p[e] > p[i1]) i1 = e;
        }
        float c0 = 1.0f / (1.0f + expf(p[i1] - p[i0]));
        float c1 = 1.0f - c0;
        int a0 = t * 2, a1 = t * 2 + 1;
        g_conf[a0] = c0;
        g_conf[a1] = c1;
        int p0 = atomicAdd(&g_cnt[i0], 1);
        g_list[i0 * T_TOK + p0] = a0;
        int p1 = atomicAdd(&g_cnt[i1], 1);
        g_list[i1 * T_TOK + p1] = a1;
    }

    // ---- W1 cvt: 8.39M elems / (512 blk * 256 thr * 4/chunk) = 16 chunks/thread ----
    {
        const size_t NW = (size_t)NEXP * DMODEL * DFF;
        size_t idx = ((size_t)blockIdx.x * 256 + threadIdx.x) * 4;
        const size_t stride = (size_t)512 * 256 * 4;
#pragma unroll 4
        for (; idx < NW; idx += stride) {
            float4 a = *(const float4*)(W1 + idx);
            __nv_bfloat162* p1 = (__nv_bfloat162*)(g_w1b + idx);
            p1[0] = __floats2bfloat162_rn(a.x, a.y);
            p1[1] = __floats2bfloat162_rn(a.z, a.w);
        }
    }
}

// ---------------- tensor-core routed GEMM: BK=64, 3-stage, single barrier/iter ----------------
// BM=128, BN=128, 256 threads (8 warps: 4m x 2n), warp tile 32x64.  (R10/R12 machinery)
// ffn1 additionally carries blockIdx.z == NEXP worker blocks that convert W2 fp32->bf16.
template<int KDIM, int LDB, bool IS_FFN1>
__global__ void __launch_bounds__(256, 2)
k_ffn(const float* __restrict__ bias, const float* __restrict__ w2src) {
    extern __shared__ char smem[];
    const int e = blockIdx.z;

    if (IS_FFN1 && e == NEXP) {
        // W2 cvt worker: 512 blocks x 256 threads, 16 float4 chunks each
        const size_t NW = (size_t)NEXP * DFF * DMODEL;
        size_t idx = ((size_t)(blockIdx.y * gridDim.x + blockIdx.x) * 256 + threadIdx.x) * 4;
        const size_t stride = (size_t)gridDim.x * gridDim.y * 256 * 4;
#pragma unroll 4
        for (; idx < NW; idx += stride) {
            float4 b = *(const float4*)(w2src + idx);
            __nv_bfloat162* p2 = (__nv_bfloat162*)(g_w2b + idx);
            p2[0] = __floats2bfloat162_rn(b.x, b.y);
            p2[1] = __floats2bfloat162_rn(b.z, b.w);
        }
        return;
    }

    const int cnt = g_cnt[e];
    const int row0 = blockIdx.y * 128;
    if (row0 >= cnt) return;
    const int n0 = blockIdx.x * 128;
    const int tid = threadIdx.x;
    const int lane = tid & 31, warp = tid >> 5;
    const int wm = warp & 3, wn = warp >> 2;

    float* s_bias = (float*)(smem + OFF_BIAS);
    int*   s_aid  = (int*)(smem + OFF_AID);

    const __nv_bfloat16* Asrc = IS_FFN1 ? g_xnb : g_hb;
    const __nv_bfloat16* W    = (IS_FFN1 ? g_w1b : g_w2b) + (size_t)e * KDIM * LDB;

    if (tid < 128) {
        int r = row0 + tid;
        s_aid[tid]  = (r < cnt) ? g_list[e * T_TOK + r] : -1;
        s_bias[tid] = bias[e * LDB + n0 + tid];
    }
    __syncthreads();

    const uint32_t sA = sptr(smem);
    const uint32_t sB = sA + OFF_B;

    // per-thread load slots: A 1024 chunks (128 rows x 8), B 1024 chunks (64 rows x 16)
    const __nv_bfloat16* aptr[4]; int asz[4]; uint32_t aoff[4];
    const __nv_bfloat16* bptr[4]; uint32_t boff[4];
#pragma unroll
    for (int j = 0; j < 4; j++) {
        int c = tid + j * 256;
        int r = c >> 3;                 // 8 x 16B chunks per 64-col A row
        int cc = (c & 7) * 8;
        int aid = s_aid[r];
        if (aid >= 0) {
            size_t rowbase = IS_FFN1 ? (size_t)(aid >> 1) * DMODEL : (size_t)aid * DFF;
            aptr[j] = Asrc + rowbase + cc;
            asz[j] = 16;
        } else {
            aptr[j] = Asrc;
            asz[j] = 0;
        }
        aoff[j] = (uint32_t)(r * 72 + cc) * 2;

        int rb = c >> 4;                // 16 x 16B chunks per 128-col B row (64 k-rows)
        int ccb = (c & 15) * 8;
        bptr[j] = W + (size_t)rb * LDB + n0 + ccb;
        boff[j] = (uint32_t)(rb * 136 + ccb) * 2;
    }

    auto load_tiles = [&](int it, int stage) {
        int k0 = it * 64;
#pragma unroll
        for (int j = 0; j < 4; j++)
            cpasync16(sA + stage * A_ST + aoff[j], aptr[j] + k0, asz[j]);
#pragma unroll
        for (int j = 0; j < 4; j++)
            cpasync16(sB + stage * B_ST + boff[j], bptr[j] + (size_t)k0 * LDB, 16);
        asm volatile("cp.async.commit_group;\n" ::: "memory");
    };

    float acc[2][8][4] = {};

    constexpr int KT = KDIM / 64;
    load_tiles(0, 0);
    load_tiles(1, 1);
    int stage_w = 2;   // next stage to fill
    int stage_c = 0;   // stage being computed

#pragma unroll 1
    for (int it = 0; it < KT; it++) {
        if (it) __syncthreads();   // all warps done reading the stage about to be overwritten
        if (it + 2 < KT) {
            load_tiles(it + 2, stage_w);
            if (++stage_w == 3) stage_w = 0;
            asm volatile("cp.async.wait_group 2;\n" ::: "memory");
        } else if (it + 1 < KT) {
            asm volatile("cp.async.wait_group 1;\n" ::: "memory");
        } else {
            asm volatile("cp.async.wait_group 0;\n" ::: "memory");
        }
        __syncthreads();   // data of stage_c visible to all warps

        const uint32_t aBase = sA + stage_c * A_ST;
        const uint32_t bBase = sB + stage_c * B_ST;
        if (++stage_c == 3) stage_c = 0;

#pragma unroll
        for (int kk = 0; kk < 64; kk += 16) {
            uint32_t a[2][4], b[4][4];
#pragma unroll
            for (int mi = 0; mi < 2; mi++) {
                int row = wm * 32 + mi * 16 + (lane & 15);
                uint32_t addr = aBase + (uint32_t)(row * 72 + kk) * 2 + (lane >> 4) * 16;
                LDSM4(a[mi], addr);
            }
#pragma unroll
            for (int nj = 0; nj < 4; nj++) {
                int krow = kk + (lane & 15);
                int col = wn * 64 + nj * 16 + (lane >> 4) * 8;
                uint32_t addr = bBase + (uint32_t)(krow * 136 + col) * 2;
                LDSM4T(b[nj], addr);
            }
#pragma unroll
            for (int mi = 0; mi < 2; mi++)
#pragma unroll
                for (int ni = 0; ni < 8; ni++)
                    MMA16816(acc[mi][ni], a[mi], b[ni >> 1][(ni & 1) * 2], b[ni >> 1][(ni & 1) * 2 + 1]);
        }
    }

    // epilogue
#pragma unroll
    for (int mi = 0; mi < 2; mi++) {
#pragma unroll
        for (int half = 0; half < 2; half++) {
            int rl = wm * 32 + mi * 16 + (lane >> 2) + half * 8;
            if (row0 + rl >= cnt) continue;
            int aid = s_aid[rl];
            if (IS_FFN1) {
                __nv_bfloat16* hrow = g_hb + (size_t)aid * DFF + n0;
#pragma unroll
                for (int ni = 0; ni < 8; ni++) {
                    int col = wn * 64 + ni * 8 + (lane & 3) * 2;
                    float v0 = gelu_f(acc[mi][ni][half * 2 + 0] + s_bias[col]);
                    float v1 = gelu_f(acc[mi][ni][half * 2 + 1] + s_bias[col + 1]);
                    *(__nv_bfloat162*)(hrow + col) = __floats2bfloat162_rn(v0, v1);
                }
            } else {
                float cf = g_conf[aid];
                float* orow = g_o + (size_t)aid * DMODEL + n0;
#pragma unroll
                for (int ni = 0; ni < 8; ni++) {
                    int col = wn * 64 + ni * 8 + (lane & 3) * 2;
                    float2 v;
                    v.x = cf * (acc[mi][ni][half * 2 + 0] + s_bias[col]);
                    v.y = cf * (acc[mi][ni][half * 2 + 1] + s_bias[col + 1]);
                    *(float2*)(orow + col) = v;
                }
            }
        }
    }
}

// ---------------- K4: combine + residual + post-LN, TWO warps per token (float4) ----------------
// 512 threads = 16 warps = 8 tokens per block; 512 blocks -> 8192 warps (2x occupancy).
// Block 0 also re-zeroes g_cnt for the next graph replay.
__global__ void __launch_bounds__(512)
k_combine(const float* __restrict__ x, const float* __restrict__ out_g,
          const float* __restrict__ out_b, float* __restrict__ out) {
    __shared__ float2 s_red[8][2];

    if (blockIdx.x == 0 && threadIdx.x < NEXP) g_cnt[threadIdx.x] = 0;

    const int tid = threadIdx.x;
    const int tsub = tid >> 6;          // token slot within block (0..7)
    const int half = (tid >> 5) & 1;    // which warp of the pair
    const int lane = tid & 31;
    const int l64 = tid & 63;           // thread within token (0..63)
    const int t = blockIdx.x * 8 + tsub;

    const float4* o04 = (const float4*)(g_o + (size_t)(t * 2) * DMODEL);
    const float4* o14 = o04 + DMODEL / 4;
    const float4* xr4 = (const float4*)(x + (size_t)t * DMODEL);

    float4 y[2];
#pragma unroll
    for (int i = 0; i < 2; i++) {
        int d4 = l64 + 64 * i;
        float4 a = xr4[d4], b = o04[d4], c = o14[d4];
        y[i].x = a.x + b.x + c.x;
        y[i].y = a.y + b.y + c.y;
        y[i].z = a.z + b.z + c.z;
        y[i].w = a.w + b.w + c.w;
    }

    float s = 0.0f, s2 = 0.0f;
#pragma unroll
    for (int i = 0; i < 2; i++) s += (y[i].x + y[i].y) + (y[i].z + y[i].w);
#pragma unroll
    for (int off = 16; off > 0; off >>= 1) s += __shfl_xor_sync(0xffffffffu, s, off);
    if (lane == 0) s_red[tsub][half].x = s;
    __syncthreads();
    float mean = (s_red[tsub][0].x + s_red[tsub][1].x) * (1.0f / DMODEL);

#pragma unroll
    for (int i = 0; i < 2; i++) {
        float dx = y[i].x - mean, dy = y[i].y - mean, dz = y[i].z - mean, dw = y[i].w - mean;
        s2 += dx * dx + dy * dy + dz * dz + dw * dw;
    }
#pragma unroll
    for (int off = 16; off > 0; off >>= 1) s2 += __shfl_xor_sync(0xffffffffu, s2, off);
    if (lane == 0) s_red[tsub][half].y = s2;
    __syncthreads();
    float var = (s_red[tsub][0].y + s_red[tsub][1].y) * (1.0f / DMODEL);
    float rstd = rsqrtf(var + 1e-5f);

    const float4* g4 = (const float4*)out_g;
    const float4* b4 = (const float4*)out_b;
    float4* orow4 = (float4*)(out + (size_t)t * DMODEL);
#pragma unroll
    for (int i = 0; i < 2; i++) {
        int d4 = l64 + 64 * i;
        float4 g = g4[d4], b = b4[d4];
        float4 o;
        o.x = (y[i].x - mean) * rstd * g.x + b.x;
        o.y = (y[i].y - mean) * rstd * g.y + b.y;
        o.z = (y[i].z - mean) * rstd * g.z + b.z;
        o.w = (y[i].w - mean) * rstd * g.w + b.w;
        orow4[d4] = o;
    }
}

// ---------------- launch ----------------
extern "C" void kernel_launch(void* const* d_in, const int* in_sizes, int n_in,
                              void* d_out, int out_size) {
    const float* x     = (const float*)d_in[0];
    const float* Wg    = (const float*)d_in[1];
    const float* W1    = (const float*)d_in[2];
    const float* b1    = (const float*)d_in[3];
    const float* W2    = (const float*)d_in[4];
    const float* b2    = (const float*)d_in[5];
    const float* ln_g  = (const float*)d_in[6];
    const float* ln_b  = (const float*)d_in[7];
    const float* out_g = (const float*)d_in[8];
    const float* out_b = (const float*)d_in[9];
    float* out = (float*)d_out;

    cudaFuncSetAttribute(k_ffn<DMODEL, DFF, true>,
                         cudaFuncAttributeMaxDynamicSharedMemorySize, SMEM_DYN);
    cudaFuncSetAttribute(k_ffn<DFF, DMODEL, false>,
                         cudaFuncAttributeMaxDynamicSharedMemorySize, SMEM_DYN);

    k_ln_router<<<T_TOK / 8, 256>>>(x, Wg, ln_g, ln_b, W1);

    dim3 g1(DFF / 128, T_TOK / 128, NEXP + 1);   // 16 x 32 x 9 (z=8 -> W2 cvt workers)
    k_ffn<DMODEL, DFF, true><<<g1, 256, SMEM_DYN>>>(b1, W2);

    dim3 g2(DMODEL / 128, T_TOK / 128, NEXP);    // 4 x 32 x 8
    k_ffn<DFF, DMODEL, false><<<g2, 256, SMEM_DYN>>>(b2, nullptr);

    k_combine<<<T_TOK / 8, 512>>>(x, out_g, out_b, out);
}

// round 17
// speedup vs baseline: 1.0399x; 1.0022x over previous
#include <cuda_runtime.h>
#include <cuda_bf16.h>
#include <cstdint>
#include <math.h>

#define T_TOK   4096
#define DMODEL  512
#define NEXP    8
#define DFF     2048
#define NASSIGN (T_TOK * 2)

// ---------------- device scratch ----------------
__device__ __nv_bfloat16 g_xnb[T_TOK * DMODEL];                 // 4 MB  normalized input (bf16)
__device__ __nv_bfloat16 g_hb[(size_t)NASSIGN * DFF];           // 32 MB gelu activations (bf16)
__device__ float         g_o[(size_t)NASSIGN * DMODEL];         // 16 MB weighted expert outputs
__device__ __nv_bfloat16 g_w1b[(size_t)NEXP * DMODEL * DFF];    // 16.8 MB
__device__ __nv_bfloat16 g_w2b[(size_t)NEXP * DFF * DMODEL];    // 16.8 MB
__device__ int   g_cnt[NEXP];          // zero-init at load; re-zeroed by k_combine each launch
__device__ int   g_list[NEXP * T_TOK];
__device__ float g_conf[NASSIGN];

// ---------------- helpers ----------------
__device__ __forceinline__ uint32_t sptr(const void* p) {
    return (uint32_t)__cvta_generic_to_shared(p);
}
__device__ __forceinline__ void cpasync16(uint32_t dst, const void* src, int srcsize) {
    asm volatile("cp.async.cg.shared.global [%0], [%1], 16, %2;\n"
                 :: "r"(dst), "l"(src), "r"(srcsize) : "memory");
}
__device__ __forceinline__ float gelu_f(float v) {
    float inner = 0.7978845608028654f * (v + 0.044715f * v * v * v);
    float t;
    asm("tanh.approx.f32 %0, %1;" : "=f"(t) : "f"(inner));
    return 0.5f * v * (1.0f + t);
}

#define LDSM4(R, addr) \
    asm volatile("ldmatrix.sync.aligned.m8n8.x4.shared.b16 {%0,%1,%2,%3}, [%4];" \
                 : "=r"(R[0]), "=r"(R[1]), "=r"(R[2]), "=r"(R[3]) : "r"(addr))
#define LDSM4T(R, addr) \
    asm volatile("ldmatrix.sync.aligned.m8n8.x4.trans.shared.b16 {%0,%1,%2,%3}, [%4];" \
                 : "=r"(R[0]), "=r"(R[1]), "=r"(R[2]), "=r"(R[3]) : "r"(addr))
#define MMA16816(C, A, B0, B1) \
    asm volatile("mma.sync.aligned.m16n8k16.row.col.f32.bf16.bf16.f32 " \
                 "{%0,%1,%2,%3}, {%4,%5,%6,%7}, {%8,%9}, {%0,%1,%2,%3};" \
                 : "+f"(C[0]), "+f"(C[1]), "+f"(C[2]), "+f"(C[3]) \
                 : "r"(A[0]), "r"(A[1]), "r"(A[2]), "r"(A[3]), "r"(B0), "r"(B1))

// smem staging (dynamic): 3-stage pipeline, BK=64
#define A_ST 18432              /* 128 rows x 72 bf16 (64 data + 8 pad) */
#define B_ST 17408              /* 64 rows x 136 bf16 */
#define OFF_B    (3 * A_ST)     /* 55296 */
#define OFF_BIAS (OFF_B + 3 * B_ST)   /* 107520 */
#define OFF_AID  (OFF_BIAS + 512)     /* 108032 */
#define SMEM_DYN (OFF_AID + 512)      /* 108544 */

// ---------------- K1: LayerNorm + router (one WARP per token) | W1 cvt (dedicated blocks) ----
// Blocks 0..511: 8 warps = 8 tokens each (LN + router only).
// Blocks 512..767: W1 fp32 -> bf16 streaming conversion only (runs concurrently).
__global__ void k_ln_router(const float* __restrict__ x, const float* __restrict__ Wg,
                            const float* __restrict__ ln_g, const float* __restrict__ ln_b,
                            const float* __restrict__ W1) {
    if (blockIdx.x >= 512) {
        // ---- W1 cvt: 2.097M float4 chunks over 256 blocks x 256 threads = 32 chunks/thread ----
        const size_t NW = (size_t)NEXP * DMODEL * DFF;
        size_t idx = ((size_t)(blockIdx.x - 512) * 256 + threadIdx.x) * 4;
        const size_t stride = (size_t)256 * 256 * 4;
#pragma unroll 4
        for (; idx < NW; idx += stride) {
            float4 a = *(const float4*)(W1 + idx);
            __nv_bfloat162* p1 = (__nv_bfloat162*)(g_w1b + idx);
            p1[0] = __floats2bfloat162_rn(a.x, a.y);
            p1[1] = __floats2bfloat162_rn(a.z, a.w);
        }
        return;
    }

    const int warp = threadIdx.x >> 5, lane = threadIdx.x & 31;
    const int t = blockIdx.x * 8 + warp;
    const float* xr = x + (size_t)t * DMODEL;

    float v[16];
#pragma unroll
    for (int i = 0; i < 16; i++) v[i] = xr[lane + 32 * i];

    float s = 0.0f;
#pragma unroll
    for (int i = 0; i < 16; i++) s += v[i];
#pragma unroll
    for (int off = 16; off > 0; off >>= 1) s += __shfl_xor_sync(0xffffffffu, s, off);
    float mean = s * (1.0f / DMODEL);

    float s2 = 0.0f;
#pragma unroll
    for (int i = 0; i < 16; i++) { float d = v[i] - mean; s2 += d * d; }
#pragma unroll
    for (int off = 16; off > 0; off >>= 1) s2 += __shfl_xor_sync(0xffffffffu, s2, off);
    float rstd = rsqrtf(s2 * (1.0f / DMODEL) + 1e-5f);

    float xn[16];
    __nv_bfloat16* xnb = g_xnb + (size_t)t * DMODEL;
#pragma unroll
    for (int i = 0; i < 16; i++) {
        int d = lane + 32 * i;
        xn[i] = (v[i] - mean) * rstd * ln_g[d] + ln_b[d];
        xnb[d] = __float2bfloat16(xn[i]);
    }

    float p[NEXP];
#pragma unroll
    for (int e = 0; e < NEXP; e++) p[e] = 0.0f;
#pragma unroll
    for (int i = 0; i < 16; i++) {
        const float4* wr = (const float4*)(Wg + (size_t)(lane + 32 * i) * NEXP);
        float4 w0 = wr[0], w1 = wr[1];
        p[0] += xn[i] * w0.x; p[1] += xn[i] * w0.y;
        p[2] += xn[i] * w0.z; p[3] += xn[i] * w0.w;
        p[4] += xn[i] * w1.x; p[5] += xn[i] * w1.y;
        p[6] += xn[i] * w1.z; p[7] += xn[i] * w1.w;
    }
#pragma unroll
    for (int e = 0; e < NEXP; e++) {
#pragma unroll
        for (int off = 16; off > 0; off >>= 1)
            p[e] += __shfl_xor_sync(0xffffffffu, p[e], off);
    }

    if (lane == 0) {
        int i0 = 0;
#pragma unroll
        for (int e = 1; e < NEXP; e++) if (p[e] > p[i0]) i0 = e;
        int i1 = -1;
#pragma unroll
        for (int e = 0; e < NEXP; e++) {
            if (e == i0) continue;
            if (i1 < 0 || p[e] > p[i1]) i1 = e;
        }
        float c0 = 1.0f / (1.0f + expf(p[i1] - p[i0]));
        float c1 = 1.0f - c0;
        int a0 = t * 2, a1 = t * 2 + 1;
        g_conf[a0] = c0;
        g_conf[a1] = c1;
        int p0 = atomicAdd(&g_cnt[i0], 1);
        g_list[i0 * T_TOK + p0] = a0;
        int p1 = atomicAdd(&g_cnt[i1], 1);
        g_list[i1 * T_TOK + p1] = a1;
    }
}

// ---------------- tensor-core routed GEMM: BK=64, 3-stage, single barrier/iter ----------------
// BM=128, BN=128, 256 threads (8 warps: 4m x 2n), warp tile 32x64.  (R10/R12 machinery)
// ffn1 additionally carries blockIdx.z == NEXP worker blocks that convert W2 fp32->bf16.
template<int KDIM, int LDB, bool IS_FFN1>
__global__ void __launch_bounds__(256, 2)
k_ffn(const float* __restrict__ bias, const float* __restrict__ w2src) {
    extern __shared__ char smem[];
    const int e = blockIdx.z;

    if (IS_FFN1 && e == NEXP) {
        // W2 cvt worker: 512 blocks x 256 threads, 16 float4 chunks each
        const size_t NW = (size_t)NEXP * DFF * DMODEL;
        size_t idx = ((size_t)(blockIdx.y * gridDim.x + blockIdx.x) * 256 + threadIdx.x) * 4;
        const size_t stride = (size_t)gridDim.x * gridDim.y * 256 * 4;
#pragma unroll 4
        for (; idx < NW; idx += stride) {
            float4 b = *(const float4*)(w2src + idx);
            __nv_bfloat162* p2 = (__nv_bfloat162*)(g_w2b + idx);
            p2[0] = __floats2bfloat162_rn(b.x, b.y);
            p2[1] = __floats2bfloat162_rn(b.z, b.w);
        }
        return;
    }

    const int cnt = g_cnt[e];
    const int row0 = blockIdx.y * 128;
    if (row0 >= cnt) return;
    const int n0 = blockIdx.x * 128;
    const int tid = threadIdx.x;
    const int lane = tid & 31, warp = tid >> 5;
    const int wm = warp & 3, wn = warp >> 2;

    float* s_bias = (float*)(smem + OFF_BIAS);
    int*   s_aid  = (int*)(smem + OFF_AID);

    const __nv_bfloat16* Asrc = IS_FFN1 ? g_xnb : g_hb;
    const __nv_bfloat16* W    = (IS_FFN1 ? g_w1b : g_w2b) + (size_t)e * KDIM * LDB;

    if (tid < 128) {
        int r = row0 + tid;
        s_aid[tid]  = (r < cnt) ? g_list[e * T_TOK + r] : -1;
        s_bias[tid] = bias[e * LDB + n0 + tid];
    }
    __syncthreads();

    const uint32_t sA = sptr(smem);
    const uint32_t sB = sA + OFF_B;

    // per-thread load slots: A 1024 chunks (128 rows x 8), B 1024 chunks (64 rows x 16)
    const __nv_bfloat16* aptr[4]; int asz[4]; uint32_t aoff[4];
    const __nv_bfloat16* bptr[4]; uint32_t boff[4];
#pragma unroll
    for (int j = 0; j < 4; j++) {
        int c = tid + j * 256;
        int r = c >> 3;                 // 8 x 16B chunks per 64-col A row
        int cc = (c & 7) * 8;
        int aid = s_aid[r];
        if (aid >= 0) {
            size_t rowbase = IS_FFN1 ? (size_t)(aid >> 1) * DMODEL : (size_t)aid * DFF;
            aptr[j] = Asrc + rowbase + cc;
            asz[j] = 16;
        } else {
            aptr[j] = Asrc;
            asz[j] = 0;
        }
        aoff[j] = (uint32_t)(r * 72 + cc) * 2;

        int rb = c >> 4;                // 16 x 16B chunks per 128-col B row (64 k-rows)
        int ccb = (c & 15) * 8;
        bptr[j] = W + (size_t)rb * LDB + n0 + ccb;
        boff[j] = (uint32_t)(rb * 136 + ccb) * 2;
    }

    auto load_tiles = [&](int it, int stage) {
        int k0 = it * 64;
#pragma unroll
        for (int j = 0; j < 4; j++)
            cpasync16(sA + stage * A_ST + aoff[j], aptr[j] + k0, asz[j]);
#pragma unroll
        for (int j = 0; j < 4; j++)
            cpasync16(sB + stage * B_ST + boff[j], bptr[j] + (size_t)k0 * LDB, 16);
        asm volatile("cp.async.commit_group;\n" ::: "memory");
    };

    float acc[2][8][4] = {};

    constexpr int KT = KDIM / 64;
    load_tiles(0, 0);
    load_tiles(1, 1);
    int stage_w = 2;   // next stage to fill
    int stage_c = 0;   // stage being computed

#pragma unroll 1
    for (int it = 0; it < KT; it++) {
        if (it) __syncthreads();   // all warps done reading the stage about to be overwritten
        if (it + 2 < KT) {
            load_tiles(it + 2, stage_w);
            if (++stage_w == 3) stage_w = 0;
            asm volatile("cp.async.wait_group 2;\n" ::: "memory");
        } else if (it + 1 < KT) {
            asm volatile("cp.async.wait_group 1;\n" ::: "memory");
        } else {
            asm volatile("cp.async.wait_group 0;\n" ::: "memory");
        }
        __syncthreads();   // data of stage_c visible to all warps

        const uint32_t aBase = sA + stage_c * A_ST;
        const uint32_t bBase = sB + stage_c * B_ST;
        if (++stage_c == 3) stage_c = 0;

#pragma unroll
        for (int kk = 0; kk < 64; kk += 16) {
            uint32_t a[2][4], b[4][4];
#pragma unroll
            for (int mi = 0; mi < 2; mi++) {
                int row = wm * 32 + mi * 16 + (lane & 15);
                uint32_t addr = aBase + (uint32_t)(row * 72 + kk) * 2 + (lane >> 4) * 16;
                LDSM4(a[mi], addr);
            }
#pragma unroll
            for (int nj = 0; nj < 4; nj++) {
                int krow = kk + (lane & 15);
                int col = wn * 64 + nj * 16 + (lane >> 4) * 8;
                uint32_t addr = bBase + (uint32_t)(krow * 136 + col) * 2;
                LDSM4T(b[nj], addr);
            }
#pragma unroll
            for (int mi = 0; mi < 2; mi++)
#pragma unroll
                for (int ni = 0; ni < 8; ni++)
                    MMA16816(acc[mi][ni], a[mi], b[ni >> 1][(ni & 1) * 2], b[ni >> 1][(ni & 1) * 2 + 1]);
        }
    }

    // epilogue
#pragma unroll
    for (int mi = 0; mi < 2; mi++) {
#pragma unroll
        for (int half = 0; half < 2; half++) {
            int rl = wm * 32 + mi * 16 + (lane >> 2) + half * 8;
            if (row0 + rl >= cnt) continue;
            int aid = s_aid[rl];
            if (IS_FFN1) {
                __nv_bfloat16* hrow = g_hb + (size_t)aid * DFF + n0;
#pragma unroll
                for (int ni = 0; ni < 8; ni++) {
                    int col = wn * 64 + ni * 8 + (lane & 3) * 2;
                    float v0 = gelu_f(acc[mi][ni][half * 2 + 0] + s_bias[col]);
                    float v1 = gelu_f(acc[mi][ni][half * 2 + 1] + s_bias[col + 1]);
                    *(__nv_bfloat162*)(hrow + col) = __floats2bfloat162_rn(v0, v1);
                }
            } else {
                float cf = g_conf[aid];
                float* orow = g_o + (size_t)aid * DMODEL + n0;
#pragma unroll
                for (int ni = 0; ni < 8; ni++) {
                    int col = wn * 64 + ni * 8 + (lane & 3) * 2;
                    float2 v;
                    v.x = cf * (acc[mi][ni][half * 2 + 0] + s_bias[col]);
                    v.y = cf * (acc[mi][ni][half * 2 + 1] + s_bias[col + 1]);
                    *(float2*)(orow + col) = v;
                }
            }
        }
    }
}

// ---------------- K4: combine + residual + post-LN, TWO warps per token (float4) ----------------
// 512 threads = 16 warps = 8 tokens per block; 512 blocks.
// Block 0 also re-zeroes g_cnt for the next graph replay.
__global__ void __launch_bounds__(512)
k_combine(const float* __restrict__ x, const float* __restrict__ out_g,
          const float* __restrict__ out_b, float* __restrict__ out) {
    __shared__ float2 s_red[8][2];

    if (blockIdx.x == 0 && threadIdx.x < NEXP) g_cnt[threadIdx.x] = 0;

    const int tid = threadIdx.x;
    const int tsub = tid >> 6;          // token slot within block (0..7)
    const int half = (tid >> 5) & 1;    // which warp of the pair
    const int lane = tid & 31;
    const int l64 = tid & 63;           // thread within token (0..63)
    const int t = blockIdx.x * 8 + tsub;

    const float4* o04 = (const float4*)(g_o + (size_t)(t * 2) * DMODEL);
    const float4* o14 = o04 + DMODEL / 4;
    const float4* xr4 = (const float4*)(x + (size_t)t * DMODEL);

    float4 y[2];
#pragma unroll
    for (int i = 0; i < 2; i++) {
        int d4 = l64 + 64 * i;
        float4 a = xr4[d4], b = o04[d4], c = o14[d4];
        y[i].x = a.x + b.x + c.x;
        y[i].y = a.y + b.y + c.y;
        y[i].z = a.z + b.z + c.z;
        y[i].w = a.w + b.w + c.w;
    }

    float s = 0.0f, s2 = 0.0f;
#pragma unroll
    for (int i = 0; i < 2; i++) s += (y[i].x + y[i].y) + (y[i].z + y[i].w);
#pragma unroll
    for (int off = 16; off > 0; off >>= 1) s += __shfl_xor_sync(0xffffffffu, s, off);
    if (lane == 0) s_red[tsub][half].x = s;
    __syncthreads();
    float mean = (s_red[tsub][0].x + s_red[tsub][1].x) * (1.0f / DMODEL);

#pragma unroll
    for (int i = 0; i < 2; i++) {
        float dx = y[i].x - mean, dy = y[i].y - mean, dz = y[i].z - mean, dw = y[i].w - mean;
        s2 += dx * dx + dy * dy + dz * dz + dw * dw;
    }
#pragma unroll
    for (int off = 16; off > 0; off >>= 1) s2 += __shfl_xor_sync(0xffffffffu, s2, off);
    if (lane == 0) s_red[tsub][half].y = s2;
    __syncthreads();
    float var = (s_red[tsub][0].y + s_red[tsub][1].y) * (1.0f / DMODEL);
    float rstd = rsqrtf(var + 1e-5f);

    const float4* g4 = (const float4*)out_g;
    const float4* b4 = (const float4*)out_b;
    float4* orow4 = (float4*)(out + (size_t)t * DMODEL);
#pragma unroll
    for (int i = 0; i < 2; i++) {
        int d4 = l64 + 64 * i;
        float4 g = g4[d4], b = b4[d4];
        float4 o;
        o.x = (y[i].x - mean) * rstd * g.x + b.x;
        o.y = (y[i].y - mean) * rstd * g.y + b.y;
        o.z = (y[i].z - mean) * rstd * g.z + b.z;
        o.w = (y[i].w - mean) * rstd * g.w + b.w;
        orow4[d4] = o;
    }
}

// ---------------- launch ----------------
extern "C" void kernel_launch(void* const* d_in, const int* in_sizes, int n_in,
                              void* d_out, int out_size) {
    const float* x     = (const float*)d_in[0];
    const float* Wg    = (const float*)d_in[1];
    const float* W1    = (const float*)d_in[2];
    const float* b1    = (const float*)d_in[3];
    const float* W2    = (const float*)d_in[4];
    const float* b2    = (const float*)d_in[5];
    const float* ln_g  = (const float*)d_in[6];
    const float* ln_b  = (const float*)d_in[7];
    const float* out_g = (const float*)d_in[8];
    const float* out_b = (const float*)d_in[9];
    float* out = (float*)d_out;

    cudaFuncSetAttribute(k_ffn<DMODEL, DFF, true>,
                         cudaFuncAttributeMaxDynamicSharedMemorySize, SMEM_DYN);
    cudaFuncSetAttribute(k_ffn<DFF, DMODEL, false>,
                         cudaFuncAttributeMaxDynamicSharedMemorySize, SMEM_DYN);

    // 512 LN/router blocks + 256 dedicated W1-cvt blocks, one launch
    k_ln_router<<<T_TOK / 8 + 256, 256>>>(x, Wg, ln_g, ln_b, W1);

    dim3 g1(DFF / 128, T_TOK / 128, NEXP + 1);   // 16 x 32 x 9 (z=8 -> W2 cvt workers)
    k_ffn<DMODEL, DFF, true><<<g1, 256, SMEM_DYN>>>(b1, W2);

    dim3 g2(DMODEL / 128, T_TOK / 128, NEXP);    // 4 x 32 x 8
    k_ffn<DFF, DMODEL, false><<<g2, 256, SMEM_DYN>>>(b2, nullptr);

    k_combine<<<T_TOK / 8, 512>>>(x, out_g, out_b, out);
}